// round 5
// baseline (speedup 1.0000x reference)
#include <cuda_runtime.h>
#include <cstdint>
#include <cstddef>

#define BTILE    28      // batches per CTA (grid 147, one wave on 148 SMs)
#define GPB      4       // batch groups per block
#define BPG      7       // batches per group
#define S_LEN    256
#define F_IN     5
#define HID      64
#define GATES    256
#define NTHREADS 256

typedef unsigned long long ull;

// ---------- packed f32x2 helpers (sm_100a) ----------
__device__ __forceinline__ ull pk2(float a, float b) {
    ull r;
    asm("mov.b64 %0, {%1, %2};" : "=l"(r) : "r"(__float_as_uint(a)), "r"(__float_as_uint(b)));
    return r;
}
__device__ __forceinline__ ull dup2(float a) {
    ull r;
    asm("mov.b64 %0, {%1, %1};" : "=l"(r) : "r"(__float_as_uint(a)));
    return r;
}
__device__ __forceinline__ void unpk(ull v, float& a, float& b) {
    unsigned int lo, hi;
    asm("mov.b64 {%0, %1}, %2;" : "=r"(lo), "=r"(hi) : "l"(v));
    a = __uint_as_float(lo);
    b = __uint_as_float(hi);
}
__device__ __forceinline__ void fma2(ull& d, ull a, ull b) {
    asm("fma.rn.f32x2 %0, %1, %2, %0;" : "+l"(d) : "l"(a), "l"(b));
}

#define BARP(id) asm volatile("bar.sync %0, 64;" :: "r"(id) : "memory")

// ---------- transcendentals (ex2-based, ~1e-6 rel) ----------
__device__ __forceinline__ float sigm(float x) {
    return __fdividef(1.0f, 1.0f + __expf(-x));
}
__device__ __forceinline__ float tanh_(float x) {
    return __fdividef(2.0f, 1.0f + __expf(-2.0f * x)) - 1.0f;
}

// gate permutation: g = m*64 + cell  ->  p = cell*4 + m
__device__ __forceinline__ int permg(int g) {
    return ((g & 63) << 2) + (g >> 6);
}

__device__ __forceinline__ float cell_update(ull aif, ull ago, float& c) {
    float iv, fv, gv, ov;
    unpk(aif, iv, fv);
    unpk(ago, gv, ov);
    float cn = sigm(fv) * c + sigm(iv) * tanh_(gv);
    c = cn;
    return sigm(ov) * tanh_(cn);
}

// acc[b][0]=(i,f), acc[b][1]=(g,o) for cell C, batches b0..b0+6.
// All 11 LDS.128 of a k4 block are hoisted ahead of the 56-FFMA2 burst so
// ptxas can software-pipeline loads of block j+1 under FMAs of block j.
__device__ __forceinline__ void gemm7(const float* __restrict__ hsrc,
                                      const float* __restrict__ Wsm,
                                      int C, int b0, ull acc[BPG][2]) {
    const float* wp = Wsm + C * 4;
    #pragma unroll 4
    for (int k4 = 0; k4 < HID; k4 += 4) {
        float4 h4[BPG];
        #pragma unroll
        for (int b = 0; b < BPG; b++)
            h4[b] = *(const float4*)(hsrc + (b0 + b) * HID + k4);
        float4 wv4[4];
        #pragma unroll
        for (int kk = 0; kk < 4; kk++)
            wv4[kk] = *(const float4*)(wp + (k4 + kk) * GATES);
        #pragma unroll
        for (int kk = 0; kk < 4; kk++) {
            ull wif = pk2(wv4[kk].x, wv4[kk].y);
            ull wgo = pk2(wv4[kk].z, wv4[kk].w);
            #pragma unroll
            for (int b = 0; b < BPG; b++) {
                float hs = (kk == 0) ? h4[b].x : (kk == 1) ? h4[b].y
                         : (kk == 2) ? h4[b].z : h4[b].w;
                ull hv = dup2(hs);
                fma2(acc[b][0], wif, hv);
                fma2(acc[b][1], wgo, hv);
            }
        }
    }
}

__device__ __forceinline__ float mlp_head(const float* __restrict__ hb,
                                          const float* __restrict__ w1,
                                          const float* __restrict__ b1,
                                          const float* __restrict__ w2,
                                          const float* __restrict__ b2) {
    float acc = b2[0];
    #pragma unroll 4
    for (int u = 0; u < 16; u++) {
        float s = b1[u];
        #pragma unroll 8
        for (int k = 0; k < HID; k++) s += hb[k] * w1[u * HID + k];
        acc += fmaxf(s, 0.0f) * w2[u];
    }
    return sigm(acc);
}

__global__ void __launch_bounds__(NTHREADS, 1)
lstm_behavior_kernel(const float* __restrict__ x,
                     const float* __restrict__ w_ih0, const float* __restrict__ w_hh0,
                     const float* __restrict__ b_ih0, const float* __restrict__ b_hh0,
                     const float* __restrict__ w_ih1, const float* __restrict__ w_hh1,
                     const float* __restrict__ b_ih1, const float* __restrict__ b_hh1,
                     const float* __restrict__ eng_w1, const float* __restrict__ eng_b1,
                     const float* __restrict__ eng_w2, const float* __restrict__ eng_b2,
                     const float* __restrict__ prop_w1, const float* __restrict__ prop_b1,
                     const float* __restrict__ prop_w2, const float* __restrict__ prop_b2,
                     const float* __restrict__ seg_w, const float* __restrict__ seg_b,
                     float* __restrict__ out, int Btot) {
    extern __shared__ float smf[];
    float* W0  = smf;                       // [64][256] w_hh0, k-major, permuted
    float* W1i = W0  + HID * GATES;         // [64][256] w_ih1
    float* W1h = W1i + HID * GATES;         // [64][256] w_hh1
    float* HA0 = W1h + HID * GATES;         // [28][64] layer0 h, ping
    float* HA1 = HA0 + BTILE * HID;         // [28][64] layer0 h, pong
    float* HB0 = HA1 + BTILE * HID;         // [28][64] layer1 h, ping
    float* HB1 = HB0 + BTILE * HID;         // [28][64] layer1 h, pong
    float* XS  = HB1 + BTILE * HID;         // [2][4][35] x staging, double-buffered

    const int tid = threadIdx.x;

    // ---- prologue: load + permute recurrent weights into SMEM ----
    for (int idx = tid; idx < HID * GATES; idx += NTHREADS) {
        int g = idx >> 6, k = idx & 63;
        int p = permg(g);
        W0 [k * GATES + p] = w_hh0[idx];
        W1i[k * GATES + p] = w_ih1[idx];
        W1h[k * GATES + p] = w_hh1[idx];
    }
    for (int idx = tid; idx < BTILE * HID; idx += NTHREADS) {
        HA0[idx] = 0.0f;
        HB0[idx] = 0.0f;
    }

    const int w    = tid >> 5;
    const int lane = tid & 31;
    const int bg   = w >> 1;          // batch group 0..3 (7 batches each)
    const int ch   = w & 1;           // cell half
    const int C    = ch * 32 + lane;  // my cell 0..63
    const int b0   = bg * BPG;
    const int plid = ch * 32 + lane;  // pair-local tid 0..63
    const int barid = bg + 1;

    // ---- register-resident w_ih0 and biases ----
    float4 wxr[F_IN];
    #pragma unroll
    for (int f = 0; f < F_IN; f++) {
        wxr[f].x = w_ih0[(0 * HID + C) * F_IN + f];
        wxr[f].y = w_ih0[(1 * HID + C) * F_IN + f];
        wxr[f].z = w_ih0[(2 * HID + C) * F_IN + f];
        wxr[f].w = w_ih0[(3 * HID + C) * F_IN + f];
    }
    ull b0if = pk2(b_ih0[C] + b_hh0[C],             b_ih0[HID + C] + b_hh0[HID + C]);
    ull b0go = pk2(b_ih0[2 * HID + C] + b_hh0[2 * HID + C],
                   b_ih0[3 * HID + C] + b_hh0[3 * HID + C]);
    ull b1if = pk2(b_ih1[C] + b_hh1[C],             b_ih1[HID + C] + b_hh1[HID + C]);
    ull b1go = pk2(b_ih1[2 * HID + C] + b_hh1[2 * HID + C],
                   b_ih1[3 * HID + C] + b_hh1[3 * HID + C]);

    // ---- x staging setup (clamped for the remainder CTA) ----
    const bool xload = (plid < BPG * F_IN);            // plid < 35
    const int  xb = plid / F_IN, xf = plid - xb * F_IN;
    int gxb = blockIdx.x * BTILE + b0 + xb;
    if (gxb > Btot - 1) gxb = Btot - 1;
    const float* xrow = x + (size_t)gxb * (S_LEN * F_IN) + xf;
    float* xs0 = XS + bg * (BPG * F_IN);               // parity-0 slot
    float* xs1 = XS + (GPB + bg) * (BPG * F_IN);       // parity-1 slot

    float xreg = 0.0f;
    if (xload) {
        xs0[plid] = xrow[0];       // stage t=0
        xreg = xrow[F_IN];         // prefetch t=1
    }

    float cA[BPG], cB[BPG];
    #pragma unroll
    for (int b = 0; b < BPG; b++) { cA[b] = 0.0f; cB[b] = 0.0f; }

    __syncthreads();   // weights + HA0/HB0 zero + XS(0) visible

    for (int t = 0; t < S_LEN; ++t) {
        const int par = t & 1;
        const float* HAc = par ? HA1 : HA0;
        float*       HAn = par ? HA0 : HA1;
        const float* HBc = par ? HB1 : HB0;
        float*       HBn = par ? HB0 : HB1;
        const float* xcur = par ? xs1 : xs0;
        float*       xnxt = par ? xs0 : xs1;

        // ===== layer 0: gates = B0 + x*W_ih0 + hA(t-1)*W_hh0 =====
        ull acc[BPG][2];
        #pragma unroll
        for (int b = 0; b < BPG; b++) { acc[b][0] = b0if; acc[b][1] = b0go; }
        #pragma unroll
        for (int f = 0; f < F_IN; ++f) {
            ull wif = pk2(wxr[f].x, wxr[f].y);
            ull wgo = pk2(wxr[f].z, wxr[f].w);
            #pragma unroll
            for (int b = 0; b < BPG; b++) {
                ull xv = dup2(xcur[b * F_IN + f]);
                fma2(acc[b][0], wif, xv);
                fma2(acc[b][1], wgo, xv);
            }
        }
        gemm7(HAc, W0, C, b0, acc);

        float hn[BPG];
        #pragma unroll
        for (int b = 0; b < BPG; b++)
            hn[b] = cell_update(acc[b][0], acc[b][1], cA[b]);

        // store hA(t) into the pong buffer
        #pragma unroll
        for (int b = 0; b < BPG; b++)
            HAn[(b0 + b) * HID + C] = hn[b];

        // stage x(t+1); prefetch x(t+2)
        if (xload) {
            xnxt[plid] = xreg;
            int tn = (t + 2 < S_LEN) ? (t + 2) : (S_LEN - 1);
            xreg = xrow[tn * F_IN];
        }

        // ===== layer 1, part 1: hB(t-1)*W_hh1 — independent of hA(t) =====
        ull acc2[BPG][2];
        #pragma unroll
        for (int b = 0; b < BPG; b++) { acc2[b][0] = b1if; acc2[b][1] = b1go; }
        gemm7(HBc, W1h, C, b0, acc2);

        BARP(barid);      // publish hA(t) — hidden behind the W1h gemm above

        // ===== layer 1, part 2: + hA(t)*W_ih1 =====
        gemm7(HAn, W1i, C, b0, acc2);

        #pragma unroll
        for (int b = 0; b < BPG; b++)
            hn[b] = cell_update(acc2[b][0], acc2[b][1], cB[b]);

        #pragma unroll
        for (int b = 0; b < BPG; b++)
            HBn[(b0 + b) * HID + C] = hn[b];

        BARP(barid);      // publish hB(t) and XS(t+1)
    }
    __syncthreads();   // final HB0 visible block-wide (S_LEN even -> parity 0)

    // ---- heads: one thread per batch element of this tile ----
    if (tid < BTILE) {
        int b = blockIdx.x * BTILE + tid;
        if (b < Btot) {
            const float* hb = HB0 + tid * HID;
            out[b]        = mlp_head(hb, eng_w1, eng_b1, eng_w2, eng_b2);
            out[Btot + b] = mlp_head(hb, prop_w1, prop_b1, prop_w2, prop_b2);
            #pragma unroll
            for (int j = 0; j < 5; j++) {
                float s = seg_b[j];
                #pragma unroll 8
                for (int k = 0; k < HID; k++) s += hb[k] * seg_w[j * HID + k];
                out[2 * Btot + b * 5 + j] = s;
            }
        }
    }
}

extern "C" void kernel_launch(void* const* d_in, const int* in_sizes, int n_in,
                              void* d_out, int out_size) {
    const float* x       = (const float*)d_in[0];
    const float* w_ih0   = (const float*)d_in[1];
    const float* w_hh0   = (const float*)d_in[2];
    const float* b_ih0   = (const float*)d_in[3];
    const float* b_hh0   = (const float*)d_in[4];
    const float* w_ih1   = (const float*)d_in[5];
    const float* w_hh1   = (const float*)d_in[6];
    const float* b_ih1   = (const float*)d_in[7];
    const float* b_hh1   = (const float*)d_in[8];
    const float* eng_w1  = (const float*)d_in[9];
    const float* eng_b1  = (const float*)d_in[10];
    const float* eng_w2  = (const float*)d_in[11];
    const float* eng_b2  = (const float*)d_in[12];
    const float* prop_w1 = (const float*)d_in[13];
    const float* prop_b1 = (const float*)d_in[14];
    const float* prop_w2 = (const float*)d_in[15];
    const float* prop_b2 = (const float*)d_in[16];
    const float* seg_w   = (const float*)d_in[17];
    const float* seg_b   = (const float*)d_in[18];
    float* out = (float*)d_out;

    int Btot = in_sizes[0] / (S_LEN * F_IN);        // 4096
    int grid = (Btot + BTILE - 1) / BTILE;          // 147

    size_t smem = (size_t)(3 * HID * GATES + 4 * BTILE * HID +
                           2 * GPB * BPG * F_IN) * sizeof(float);   // 226,400 B
    cudaFuncSetAttribute(lstm_behavior_kernel,
                         cudaFuncAttributeMaxDynamicSharedMemorySize, (int)smem);

    lstm_behavior_kernel<<<grid, NTHREADS, smem>>>(
        x, w_ih0, w_hh0, b_ih0, b_hh0, w_ih1, w_hh1, b_ih1, b_hh1,
        eng_w1, eng_b1, eng_w2, eng_b2, prop_w1, prop_b1, prop_w2, prop_b2,
        seg_w, seg_b, out, Btot);
}

// round 6
// speedup vs baseline: 1.0107x; 1.0107x over previous
#include <cuda_runtime.h>
#include <cstdint>
#include <cstddef>

#define BTILE    28      // batches per CTA (grid 147, one wave on 148 SMs)
#define GPB      4       // batch groups per block
#define BPG      7       // batches per group
#define S_LEN    256
#define F_IN     5
#define HID      64
#define GATES    256
#define NTHREADS 512

typedef unsigned long long ull;

// ---------- packed f32x2 helpers (sm_100a) ----------
__device__ __forceinline__ ull pk2(float a, float b) {
    ull r;
    asm("mov.b64 %0, {%1, %2};" : "=l"(r) : "r"(__float_as_uint(a)), "r"(__float_as_uint(b)));
    return r;
}
__device__ __forceinline__ ull dup2(float a) {
    ull r;
    asm("mov.b64 %0, {%1, %1};" : "=l"(r) : "r"(__float_as_uint(a)));
    return r;
}
__device__ __forceinline__ void unpk(ull v, float& a, float& b) {
    unsigned int lo, hi;
    asm("mov.b64 {%0, %1}, %2;" : "=r"(lo), "=r"(hi) : "l"(v));
    a = __uint_as_float(lo);
    b = __uint_as_float(hi);
}
__device__ __forceinline__ void fma2(ull& d, ull a, ull b) {
    asm("fma.rn.f32x2 %0, %1, %2, %0;" : "+l"(d) : "l"(a), "l"(b));
}

#define BARP(id) asm volatile("bar.sync %0, 128;" :: "r"(id) : "memory")

// ---------- transcendentals (ex2-based, ~1e-6 rel) ----------
__device__ __forceinline__ float sigm(float x) {
    return __fdividef(1.0f, 1.0f + __expf(-x));
}
__device__ __forceinline__ float tanh_(float x) {
    return __fdividef(2.0f, 1.0f + __expf(-2.0f * x)) - 1.0f;
}

// gate permutation: g = m*64 + cell  ->  p = cell*4 + m
__device__ __forceinline__ int permg(int g) {
    return ((g & 63) << 2) + (g >> 6);
}

__device__ __forceinline__ float cell_update(ull aif, ull ago, float& c) {
    float iv, fv, gv, ov;
    unpk(aif, iv, fv);
    unpk(ago, gv, ov);
    float cn = sigm(fv) * c + sigm(iv) * tanh_(gv);
    c = cn;
    return sigm(ov) * tanh_(cn);
}

// acc[b][0]=(i,f), acc[b][1]=(g,o) for cell C, batches b0..b0+6
__device__ __forceinline__ void gemm7(const float* __restrict__ hsrc,
                                      const float* __restrict__ Wsm,
                                      int C, int b0, ull acc[BPG][2]) {
    const float* wp = Wsm + C * 4;
    #pragma unroll 4
    for (int k4 = 0; k4 < HID; k4 += 4) {
        float4 h4[BPG];
        #pragma unroll
        for (int b = 0; b < BPG; b++)
            h4[b] = *(const float4*)(hsrc + (b0 + b) * HID + k4);
        #pragma unroll
        for (int kk = 0; kk < 4; kk++) {
            float4 wv = *(const float4*)(wp + (k4 + kk) * GATES);
            ull wif = pk2(wv.x, wv.y);
            ull wgo = pk2(wv.z, wv.w);
            #pragma unroll
            for (int b = 0; b < BPG; b++) {
                float hs = (kk == 0) ? h4[b].x : (kk == 1) ? h4[b].y
                         : (kk == 2) ? h4[b].z : h4[b].w;
                ull hv = dup2(hs);
                fma2(acc[b][0], wif, hv);
                fma2(acc[b][1], wgo, hv);
            }
        }
    }
}

__device__ __forceinline__ float mlp_head(const float* __restrict__ hb,
                                          const float* __restrict__ w1,
                                          const float* __restrict__ b1,
                                          const float* __restrict__ w2,
                                          const float* __restrict__ b2) {
    float acc = b2[0];
    #pragma unroll 4
    for (int u = 0; u < 16; u++) {
        float s = b1[u];
        #pragma unroll 8
        for (int k = 0; k < HID; k++) s += hb[k] * w1[u * HID + k];
        acc += fmaxf(s, 0.0f) * w2[u];
    }
    return sigm(acc);
}

__global__ void __launch_bounds__(NTHREADS, 1)
lstm_behavior_kernel(const float* __restrict__ x,
                     const float* __restrict__ w_ih0, const float* __restrict__ w_hh0,
                     const float* __restrict__ b_ih0, const float* __restrict__ b_hh0,
                     const float* __restrict__ w_ih1, const float* __restrict__ w_hh1,
                     const float* __restrict__ b_ih1, const float* __restrict__ b_hh1,
                     const float* __restrict__ eng_w1, const float* __restrict__ eng_b1,
                     const float* __restrict__ eng_w2, const float* __restrict__ eng_b2,
                     const float* __restrict__ prop_w1, const float* __restrict__ prop_b1,
                     const float* __restrict__ prop_w2, const float* __restrict__ prop_b2,
                     const float* __restrict__ seg_w, const float* __restrict__ seg_b,
                     float* __restrict__ out, int Btot) {
    extern __shared__ float smf[];
    float* W0  = smf;                       // [64][256] w_hh0, k-major, permuted
    float* W1i = W0  + HID * GATES;         // [64][256] w_ih1
    float* W1h = W1i + HID * GATES;         // [64][256] w_hh1
    float* HA0 = W1h + HID * GATES;         // [28][64] layer0 h, parity 0
    float* HA1 = HA0 + BTILE * HID;         // [28][64] layer0 h, parity 1
    float* HB0 = HA1 + BTILE * HID;         // [28][64] layer1 h, parity 0
    float* HB1 = HB0 + BTILE * HID;         // [28][64] layer1 h, parity 1
    float* XS  = HB1 + BTILE * HID;         // [2][4][35] x staging

    const int tid = threadIdx.x;

    // ---- prologue: load + permute recurrent weights into SMEM ----
    for (int idx = tid; idx < HID * GATES; idx += NTHREADS) {
        int g = idx >> 6, k = idx & 63;
        int p = permg(g);
        W0 [k * GATES + p] = w_hh0[idx];
        W1i[k * GATES + p] = w_ih1[idx];
        W1h[k * GATES + p] = w_hh1[idx];
    }
    for (int idx = tid; idx < BTILE * HID; idx += NTHREADS) {
        HA0[idx] = 0.0f; HA1[idx] = 0.0f;
        HB0[idx] = 0.0f; HB1[idx] = 0.0f;
    }

    const int wid  = tid >> 5;
    const int lane = tid & 31;
    const int bg   = wid & 3;         // batch group 0..3 (SMSP = wid%4 = bg)
    const int role = wid >> 2;        // 0,1 = layer0 cell-halves; 2,3 = layer1
    const int b0   = bg * BPG;
    const int barid = bg + 1;

    float cst[BPG];                   // cA for layer0 warps, cB for layer1 warps
    #pragma unroll
    for (int b = 0; b < BPG; b++) cst[b] = 0.0f;

    if (role < 2) {
        // ================= LAYER-0 persona =================
        const int C = role * 32 + lane;

        float4 wxr[F_IN];
        #pragma unroll
        for (int f = 0; f < F_IN; f++) {
            wxr[f].x = w_ih0[(0 * HID + C) * F_IN + f];
            wxr[f].y = w_ih0[(1 * HID + C) * F_IN + f];
            wxr[f].z = w_ih0[(2 * HID + C) * F_IN + f];
            wxr[f].w = w_ih0[(3 * HID + C) * F_IN + f];
        }
        ull b0if = pk2(b_ih0[C] + b_hh0[C],             b_ih0[HID + C] + b_hh0[HID + C]);
        ull b0go = pk2(b_ih0[2 * HID + C] + b_hh0[2 * HID + C],
                       b_ih0[3 * HID + C] + b_hh0[3 * HID + C]);

        // x staging: 64 layer0 threads per bg, 35 active
        const int plid = role * 32 + lane;
        const bool xload = (plid < BPG * F_IN);
        const int  xb = plid / F_IN, xf = plid - xb * F_IN;
        int gxb = blockIdx.x * BTILE + b0 + xb;
        if (gxb > Btot - 1) gxb = Btot - 1;
        const float* xrow = x + (size_t)gxb * (S_LEN * F_IN) + xf;
        float* xs0 = XS + bg * (BPG * F_IN);
        float* xs1 = XS + (GPB + bg) * (BPG * F_IN);

        float xreg = 0.0f;
        if (xload) {
            xs0[plid] = xrow[0];
            xreg = xrow[F_IN];
        }
        __syncthreads();   // weights + zeroed H + XS(0) visible

        for (int t = 0; t < S_LEN; ++t) {
            const int par = t & 1;
            const float* HAc = par ? HA0 : HA1;   // hA(t-1) at parity (t-1)&1
            float*       HAn = par ? HA1 : HA0;   // write parity t&1
            const float* xcur = par ? xs1 : xs0;
            float*       xnxt = par ? xs0 : xs1;

            ull acc[BPG][2];
            #pragma unroll
            for (int b = 0; b < BPG; b++) { acc[b][0] = b0if; acc[b][1] = b0go; }
            #pragma unroll
            for (int f = 0; f < F_IN; ++f) {
                ull wif = pk2(wxr[f].x, wxr[f].y);
                ull wgo = pk2(wxr[f].z, wxr[f].w);
                #pragma unroll
                for (int b = 0; b < BPG; b++) {
                    ull xv = dup2(xcur[b * F_IN + f]);
                    fma2(acc[b][0], wif, xv);
                    fma2(acc[b][1], wgo, xv);
                }
            }
            gemm7(HAc, W0, C, b0, acc);

            float hn[BPG];
            #pragma unroll
            for (int b = 0; b < BPG; b++)
                hn[b] = cell_update(acc[b][0], acc[b][1], cst[b]);
            #pragma unroll
            for (int b = 0; b < BPG; b++)
                HAn[(b0 + b) * HID + C] = hn[b];

            if (xload) {
                xnxt[plid] = xreg;
                int tn = (t + 2 < S_LEN) ? (t + 2) : (S_LEN - 1);
                xreg = xrow[tn * F_IN];
            }

            BARP(barid);   // slot boundary: publish hA(t), XS(t+1)
        }
        BARP(barid);       // final slot: layer1 runs step 255; layer0 idles
    } else {
        // ================= LAYER-1 persona =================
        const int C = (role - 2) * 32 + lane;

        ull b1if = pk2(b_ih1[C] + b_hh1[C],             b_ih1[HID + C] + b_hh1[HID + C]);
        ull b1go = pk2(b_ih1[2 * HID + C] + b_hh1[2 * HID + C],
                       b_ih1[3 * HID + C] + b_hh1[3 * HID + C]);

        __syncthreads();   // weights + zeroed H visible
        BARP(barid);       // slot 0: layer0 computes step 0; layer1 idles

        for (int s = 0; s < S_LEN; ++s) {     // slot t = s+1, processing step s
            const int sp = s & 1;
            const float* HAs = sp ? HA1 : HA0;   // hA(s) at parity s&1
            const float* HBc = sp ? HB0 : HB1;   // hB(s-1) at parity (s-1)&1
            float*       HBn = sp ? HB1 : HB0;   // write parity s&1

            ull acc[BPG][2];
            #pragma unroll
            for (int b = 0; b < BPG; b++) { acc[b][0] = b1if; acc[b][1] = b1go; }
            gemm7(HAs, W1i, C, b0, acc);
            gemm7(HBc, W1h, C, b0, acc);

            float hn[BPG];
            #pragma unroll
            for (int b = 0; b < BPG; b++)
                hn[b] = cell_update(acc[b][0], acc[b][1], cst[b]);
            #pragma unroll
            for (int b = 0; b < BPG; b++)
                HBn[(b0 + b) * HID + C] = hn[b];

            BARP(barid);   // slot boundary: publish hB(s)
        }
    }
    __syncthreads();   // final hB (parity 1, s=255) visible block-wide

    // ---- heads: one thread per batch element of this tile ----
    if (tid < BTILE) {
        int b = blockIdx.x * BTILE + tid;
        if (b < Btot) {
            const float* hb = HB1 + tid * HID;   // s=255 -> parity 1
            out[b]        = mlp_head(hb, eng_w1, eng_b1, eng_w2, eng_b2);
            out[Btot + b] = mlp_head(hb, prop_w1, prop_b1, prop_w2, prop_b2);
            #pragma unroll
            for (int j = 0; j < 5; j++) {
                float s = seg_b[j];
                #pragma unroll 8
                for (int k = 0; k < HID; k++) s += hb[k] * seg_w[j * HID + k];
                out[2 * Btot + b * 5 + j] = s;
            }
        }
    }
}

extern "C" void kernel_launch(void* const* d_in, const int* in_sizes, int n_in,
                              void* d_out, int out_size) {
    const float* x       = (const float*)d_in[0];
    const float* w_ih0   = (const float*)d_in[1];
    const float* w_hh0   = (const float*)d_in[2];
    const float* b_ih0   = (const float*)d_in[3];
    const float* b_hh0   = (const float*)d_in[4];
    const float* w_ih1   = (const float*)d_in[5];
    const float* w_hh1   = (const float*)d_in[6];
    const float* b_ih1   = (const float*)d_in[7];
    const float* b_hh1   = (const float*)d_in[8];
    const float* eng_w1  = (const float*)d_in[9];
    const float* eng_b1  = (const float*)d_in[10];
    const float* eng_w2  = (const float*)d_in[11];
    const float* eng_b2  = (const float*)d_in[12];
    const float* prop_w1 = (const float*)d_in[13];
    const float* prop_b1 = (const float*)d_in[14];
    const float* prop_w2 = (const float*)d_in[15];
    const float* prop_b2 = (const float*)d_in[16];
    const float* seg_w   = (const float*)d_in[17];
    const float* seg_b   = (const float*)d_in[18];
    float* out = (float*)d_out;

    int Btot = in_sizes[0] / (S_LEN * F_IN);        // 4096
    int grid = (Btot + BTILE - 1) / BTILE;          // 147

    size_t smem = (size_t)(3 * HID * GATES + 4 * BTILE * HID +
                           2 * GPB * BPG * F_IN) * sizeof(float);   // 226,400 B
    cudaFuncSetAttribute(lstm_behavior_kernel,
                         cudaFuncAttributeMaxDynamicSharedMemorySize, (int)smem);

    lstm_behavior_kernel<<<grid, NTHREADS, smem>>>(
        x, w_ih0, w_hh0, b_ih0, b_hh0, w_ih1, w_hh1, b_ih1, b_hh1,
        eng_w1, eng_b1, eng_w2, eng_b2, prop_w1, prop_b1, prop_w2, prop_b2,
        seg_w, seg_b, out, Btot);
}